// round 11
// baseline (speedup 1.0000x reference)
#include <cuda_runtime.h>
#include <cuda_fp16.h>
#include <cstdint>

// Bilinear out[b,i,j,k] = sum_{p,q} x1[b,i,p] W[k,p,q] x2[b,j,q] + bias[k]
// B=8, L=256, D1=D2=512, K=64.
// GEMM1: TMP[m=(b,i)][n=(k,q)] = X1[2048,512] . Wt[(k,q)][p]   (NT, inner 512)
// GEMM2: per b: C[j][r=(i,k)]  = X2_b[j][q] . TMP_b[r][q]      (NT, inner 512)
// Single-pass fp16 HMMA. 64x64 warp tile (4 warps/CTA) halves B-fragment
// LDSM duplication -> smem crossbar 75% of tensor instead of 100% co-bound.

#define DI __device__ __forceinline__

#define MT 128          // CTA m tile
#define NTL 128         // CTA n tile
#define KC 64           // k elements per chunk (128B rows fp16)
#define NCHUNK 8        // 512/64

#define TILE_B 16384            // 128 rows x 128B
#define STAGE_B 32768           // A|B
#define NSTAGE 3
#define SMEM_BYTES (NSTAGE*STAGE_B + 1024)

// ---------------- scratch (device globals; allocs forbidden) ----------------
__device__ __half g_x1h[2048*512];
__device__ __half g_x2h[2048*512];
__device__ __half g_wth[64*512*512];    // Wt[k][q][p]
__device__ __half g_th[2048u*32768u];   // TMP [m][n]

// ---------------- PTX helpers ----------------
DI uint32_t smem_u32(const void* p) {
    uint32_t a;
    asm("{ .reg .u64 t; cvta.to.shared.u64 t, %1; cvt.u32.u64 %0, t; }"
        : "=r"(a) : "l"(p));
    return a;
}
DI void cp16(uint32_t dst, const void* src) {
    asm volatile("cp.async.cg.shared.global [%0], [%1], 16;"
                 :: "r"(dst), "l"(src) : "memory");
}
#define CP_COMMIT() asm volatile("cp.async.commit_group;" ::: "memory")
#define CP_WAIT1()  asm volatile("cp.async.wait_group 1;"  ::: "memory")
#define CP_WAIT0()  asm volatile("cp.async.wait_group 0;"  ::: "memory")

DI void ldsm4(uint32_t addr, uint32_t r[4]) {
    asm volatile("ldmatrix.sync.aligned.m8n8.x4.shared.b16 {%0,%1,%2,%3}, [%4];"
        : "=r"(r[0]), "=r"(r[1]), "=r"(r[2]), "=r"(r[3]) : "r"(addr));
}
DI void mma16816(float c[4], const uint32_t a[4], uint32_t b0, uint32_t b1) {
    asm volatile("mma.sync.aligned.m16n8k16.row.col.f32.f16.f16.f32 "
        "{%0,%1,%2,%3}, {%4,%5,%6,%7}, {%8,%9}, {%0,%1,%2,%3};"
        : "+f"(c[0]), "+f"(c[1]), "+f"(c[2]), "+f"(c[3])
        : "r"(a[0]), "r"(a[1]), "r"(a[2]), "r"(a[3]), "r"(b0), "r"(b1));
}

// ---------------- stage loader: A,B K-major tiles (128 threads) ----------
DI void stage_load(const __half* __restrict__ gA, const __half* __restrict__ gB,
                   uint32_t sbase, int chunk, int tid) {
    #pragma unroll
    for (int i = 0; i < 8; i++) {
        int g   = tid + i * 128;
        int row = g >> 3;
        int c   = g & 7;
        uint32_t dst = sbase + (uint32_t)(row * 128 + ((c ^ (row & 7)) << 4));
        size_t   src = (size_t)row * 512 + chunk * KC + c * 8;
        cp16(dst,          gA + src);
        cp16(dst + TILE_B, gB + src);
    }
    CP_COMMIT();
}

// ---------------- compute one 64-wide K chunk (warp tile 64x64) ----------
DI void compute_stage(uint32_t s, int wid, int lane, float acc[4][8][4]) {
    const int wm = (wid & 1) * 64;
    const int wn = (wid >> 1) * 64;
    const int lr = lane & 15;
    const int ls = lane >> 4;
    const uint32_t sA = s;
    const uint32_t sB = s + TILE_B;
    #pragma unroll
    for (int ks = 0; ks < 4; ks++) {
        const int kg = ks * 2;
        uint32_t ah[4][4];
        #pragma unroll
        for (int mg = 0; mg < 4; mg++) {
            int row = wm + mg * 16 + lr;
            uint32_t off = (uint32_t)(row * 128 + (((kg + ls) ^ (row & 7)) << 4));
            ldsm4(sA + off, ah[mg]);
        }
        #pragma unroll
        for (int h = 0; h < 4; h++) {
            int row = wn + h * 16 + lr;
            uint32_t off = (uint32_t)(row * 128 + (((kg + ls) ^ (row & 7)) << 4));
            uint32_t bh[4];
            ldsm4(sB + off, bh);
            #pragma unroll
            for (int mg = 0; mg < 4; mg++) {
                mma16816(acc[mg][2*h],   ah[mg], bh[0], bh[2]);
                mma16816(acc[mg][2*h+1], ah[mg], bh[1], bh[3]);
            }
        }
    }
}

// ---------------- shared mainloop (3-stage pipeline, 1 sync/chunk) ----------
DI void gemm_core(const __half* gA, const __half* gB,
                  uint32_t s0, int tid, int wid, int lane, float acc[4][8][4]) {
    #pragma unroll
    for (int a = 0; a < 4; a++)
        #pragma unroll
        for (int b = 0; b < 8; b++)
            #pragma unroll
            for (int e = 0; e < 4; e++) acc[a][b][e] = 0.f;

    stage_load(gA, gB, s0,           0, tid);
    stage_load(gA, gB, s0 + STAGE_B, 1, tid);
    #pragma unroll 1
    for (int c = 0; c < NCHUNK; c++) {
        if (c < NCHUNK - 1) CP_WAIT1(); else CP_WAIT0();
        __syncthreads();
        if (c < NCHUNK - 2)
            stage_load(gA, gB, s0 + ((c + 2) % NSTAGE) * STAGE_B, c + 2, tid);
        compute_stage(s0 + (c % NSTAGE) * STAGE_B, wid, lane, acc);
    }
}

// ---------------- GEMM1: epilogue emits fp16 TMP ----------------
__global__ void __launch_bounds__(128, 2) k_gemm1() {
    extern __shared__ __align__(16) char dyn[];
    const int tid = threadIdx.x, wid = tid >> 5, lane = tid & 31;
    uint32_t s0 = (smem_u32(dyn) + 1023u) & ~1023u;

    const int bm = blockIdx.x * MT;    // m = b*256+i   (x = m for W L2 reuse)
    const int bn = blockIdx.y * NTL;   // n = k*512+q
    float acc[4][8][4];
    gemm_core(g_x1h + (size_t)bm * 512, g_wth + (size_t)bn * 512,
              s0, tid, wid, lane, acc);

    const int wm = (wid & 1) * 64, wn = (wid >> 1) * 64;
    const int quad = lane >> 2, tq = lane & 3;
    #pragma unroll
    for (int mg = 0; mg < 4; mg++) {
        #pragma unroll
        for (int pr = 0; pr < 2; pr++) {
            int m = bm + wm + mg * 16 + quad + pr * 8;
            size_t rowb = (size_t)m * 32768 + bn + wn + tq * 2;
            #pragma unroll
            for (int g = 0; g < 8; g++) {
                __half2 hv = __floats2half2_rn(acc[mg][g][pr * 2],
                                               acc[mg][g][pr * 2 + 1]);
                *(__half2*)(g_th + rowb + g * 8) = hv;
            }
        }
    }
}

// ---------------- GEMM2: out = X2_b . TMP_b^T + bias ----------------
__global__ void __launch_bounds__(128, 2) k_gemm2(const float* __restrict__ bias,
                                                  float* __restrict__ out) {
    extern __shared__ __align__(16) char dyn[];
    const int tid = threadIdx.x, wid = tid >> 5, lane = tid & 31;
    uint32_t s0 = (smem_u32(dyn) + 1023u) & ~1023u;

    const int bj = blockIdx.x * MT;    // j  (x = j for TMP L2 reuse)
    const int bn = blockIdx.y * NTL;   // r = i*64 + k
    const int b  = blockIdx.z;
    float acc[4][8][4];
    gemm_core(g_x2h + (size_t)b * 131072 + (size_t)bj * 512,
              g_th  + (size_t)b * 8388608 + (size_t)bn * 512,
              s0, tid, wid, lane, acc);

    const int wm = (wid & 1) * 64, wn = (wid >> 1) * 64;
    const int quad = lane >> 2, tq = lane & 3;
    const int ig = (bn + wn) >> 6;                  // constant per warp (wn mult of 64)
    const size_t obase = ((size_t)b << 22) + (size_t)ig * 16384;
    #pragma unroll
    for (int g = 0; g < 8; g++) {
        int k = g * 8 + tq * 2;
        float2 bv = *(const float2*)(bias + k);
        #pragma unroll
        for (int mg = 0; mg < 4; mg++) {
            #pragma unroll
            for (int pr = 0; pr < 2; pr++) {
                int j = bj + wm + mg * 16 + quad + pr * 8;
                float2 v;
                v.x = acc[mg][g][pr * 2]     + bv.x;
                v.y = acc[mg][g][pr * 2 + 1] + bv.y;
                *(float2*)(out + obase + (size_t)j * 64 + k) = v;
            }
        }
    }
}

// ---------------- prep: fp32 -> fp16 ----------------
__global__ void __launch_bounds__(256) k_split(const float* __restrict__ in, int which) {
    __half* oh = which ? g_x2h : g_x1h;
    int i = blockIdx.x * 256 + threadIdx.x;      // 262144 float4s
    float4 v = ((const float4*)in)[i];
    ((__half2*)oh)[2 * i]     = __floats2half2_rn(v.x, v.y);
    ((__half2*)oh)[2 * i + 1] = __floats2half2_rn(v.z, v.w);
}

// W[k][p][q] -> Wt[k][q][p] fp16 (32x32 smem transpose tiles)
__global__ void __launch_bounds__(256) k_wtrans(const float* __restrict__ W) {
    __shared__ float t[32][33];
    int k = blockIdx.z;
    int q0 = blockIdx.x * 32, p0 = blockIdx.y * 32;
    int tx = threadIdx.x & 31, ty = threadIdx.x >> 5;
    const float* Wk = W + (size_t)k * 262144;
    #pragma unroll
    for (int s = 0; s < 4; s++)
        t[ty + s * 8][tx] = Wk[(size_t)(p0 + ty + s * 8) * 512 + q0 + tx];
    __syncthreads();
    #pragma unroll
    for (int s = 0; s < 4; s++) {
        int q = q0 + ty + s * 8;
        g_wth[(size_t)k * 262144 + (size_t)q * 512 + p0 + tx] =
            __float2half_rn(t[tx][ty + s * 8]);
    }
}

// ---------------- launch ----------------
extern "C" void kernel_launch(void* const* d_in, const int* in_sizes, int n_in,
                              void* d_out, int out_size) {
    const float* x1   = (const float*)d_in[0];
    const float* x2   = (const float*)d_in[1];
    const float* w    = (const float*)d_in[2];
    const float* bias = (const float*)d_in[3];
    float* out = (float*)d_out;

    cudaFuncSetAttribute(k_gemm1, cudaFuncAttributeMaxDynamicSharedMemorySize, SMEM_BYTES);
    cudaFuncSetAttribute(k_gemm2, cudaFuncAttributeMaxDynamicSharedMemorySize, SMEM_BYTES);

    k_split<<<1024, 256>>>(x1, 0);
    k_split<<<1024, 256>>>(x2, 1);
    k_wtrans<<<dim3(16, 16, 64), 256>>>(w);
    // GEMM1: x = m (16) so a wave shares W n-tiles across all 16 m-blocks (L2 reuse)
    k_gemm1<<<dim3(16, 256), 128, SMEM_BYTES>>>();
    // GEMM2: x = j (2) so both j-blocks of a TMP n-tile are co-resident
    k_gemm2<<<dim3(2, 128, 8), 128, SMEM_BYTES>>>(bias, out);
}

// round 13
// speedup vs baseline: 1.0185x; 1.0185x over previous
#include <cuda_runtime.h>
#include <cuda_fp16.h>
#include <cstdint>

// Bilinear out[b,i,j,k] = sum_{p,q} x1[b,i,p] W[k,p,q] x2[b,j,q] + bias[k]
// B=8, L=256, D1=D2=512, K=64.
// GEMM1: TMP[m=(b,i)][n=(k,q)] = X1[2048,512] . Wt[(k,q)][p]   (NT, inner 512)
// GEMM2: per b: C[j][r=(i,k)]  = X2_b[j][q] . TMP_b[r][q]      (NT, inner 512)
// Single-pass fp16 HMMA. Round 12: CTA 64x128, 128 thr, 72KB smem ->
// 3 resident CTA streams/SM (duty-cycle stacking: each stream ~29% tensor duty).

#define DI __device__ __forceinline__

#define MT 64           // CTA m tile
#define NTL 128         // CTA n tile
#define KC 64           // k elements per chunk (128B rows fp16)
#define NCHUNK 8        // 512/64

#define TILE_A_B 8192           // 64 rows x 128B
#define TILE_B_B 16384          // 128 rows x 128B
#define STAGE_B (TILE_A_B + TILE_B_B)   // 24KB
#define NSTAGE 3
#define SMEM_BYTES (NSTAGE*STAGE_B + 1024)

// ---------------- scratch (device globals; allocs forbidden) ----------------
__device__ __half g_x1h[2048*512];
__device__ __half g_x2h[2048*512];
__device__ __half g_wth[64*512*512];    // Wt[k][q][p]
__device__ __half g_th[2048u*32768u];   // TMP [m][n]

// ---------------- PTX helpers ----------------
DI uint32_t smem_u32(const void* p) {
    uint32_t a;
    asm("{ .reg .u64 t; cvta.to.shared.u64 t, %1; cvt.u32.u64 %0, t; }"
        : "=r"(a) : "l"(p));
    return a;
}
DI void cp16(uint32_t dst, const void* src) {
    asm volatile("cp.async.cg.shared.global [%0], [%1], 16;"
                 :: "r"(dst), "l"(src) : "memory");
}
#define CP_COMMIT() asm volatile("cp.async.commit_group;" ::: "memory")
#define CP_WAIT1()  asm volatile("cp.async.wait_group 1;"  ::: "memory")
#define CP_WAIT0()  asm volatile("cp.async.wait_group 0;"  ::: "memory")

DI void ldsm4(uint32_t addr, uint32_t r[4]) {
    asm volatile("ldmatrix.sync.aligned.m8n8.x4.shared.b16 {%0,%1,%2,%3}, [%4];"
        : "=r"(r[0]), "=r"(r[1]), "=r"(r[2]), "=r"(r[3]) : "r"(addr));
}
DI void mma16816(float c[4], const uint32_t a[4], uint32_t b0, uint32_t b1) {
    asm volatile("mma.sync.aligned.m16n8k16.row.col.f32.f16.f16.f32 "
        "{%0,%1,%2,%3}, {%4,%5,%6,%7}, {%8,%9}, {%0,%1,%2,%3};"
        : "+f"(c[0]), "+f"(c[1]), "+f"(c[2]), "+f"(c[3])
        : "r"(a[0]), "r"(a[1]), "r"(a[2]), "r"(a[3]), "r"(b0), "r"(b1));
}

// ---------------- stage loader: A(64r) + B(128r) K-major tiles, 128 threads ----
DI void stage_load(const __half* __restrict__ gA, const __half* __restrict__ gB,
                   uint32_t sbase, int chunk, int tid) {
    #pragma unroll
    for (int i = 0; i < 4; i++) {                 // A: 512 granules
        int g   = tid + i * 128;
        int row = g >> 3;
        int c   = g & 7;
        uint32_t dst = sbase + (uint32_t)(row * 128 + ((c ^ (row & 7)) << 4));
        cp16(dst, gA + (size_t)row * 512 + chunk * KC + c * 8);
    }
    #pragma unroll
    for (int i = 0; i < 8; i++) {                 // B: 1024 granules
        int g   = tid + i * 128;
        int row = g >> 3;
        int c   = g & 7;
        uint32_t dst = sbase + TILE_A_B + (uint32_t)(row * 128 + ((c ^ (row & 7)) << 4));
        cp16(dst, gB + (size_t)row * 512 + chunk * KC + c * 8);
    }
    CP_COMMIT();
}

// ---------------- compute one 64-wide K chunk (4 warps, warp 32x64) ----------
DI void compute_stage(uint32_t s, int wid, int lane, float acc[2][8][4]) {
    const int wm = (wid & 1) * 32;
    const int wn = (wid >> 1) * 64;
    const int lr = lane & 15;
    const int ls = lane >> 4;
    const uint32_t sA = s;
    const uint32_t sB = s + TILE_A_B;
    #pragma unroll
    for (int ks = 0; ks < 4; ks++) {
        const int kg = ks * 2;
        uint32_t ah[2][4];
        #pragma unroll
        for (int mg = 0; mg < 2; mg++) {
            int row = wm + mg * 16 + lr;
            uint32_t off = (uint32_t)(row * 128 + (((kg + ls) ^ (row & 7)) << 4));
            ldsm4(sA + off, ah[mg]);
        }
        #pragma unroll
        for (int h = 0; h < 4; h++) {
            int row = wn + h * 16 + lr;
            uint32_t off = (uint32_t)(row * 128 + (((kg + ls) ^ (row & 7)) << 4));
            uint32_t bh[4];
            ldsm4(sB + off, bh);
            #pragma unroll
            for (int mg = 0; mg < 2; mg++) {
                mma16816(acc[mg][2*h],   ah[mg], bh[0], bh[2]);
                mma16816(acc[mg][2*h+1], ah[mg], bh[1], bh[3]);
            }
        }
    }
}

// ---------------- shared mainloop (3-stage pipeline, 1 sync/chunk) ----------
DI void gemm_core(const __half* gA, const __half* gB,
                  uint32_t s0, int tid, int wid, int lane, float acc[2][8][4]) {
    #pragma unroll
    for (int a = 0; a < 2; a++)
        #pragma unroll
        for (int b = 0; b < 8; b++)
            #pragma unroll
            for (int e = 0; e < 4; e++) acc[a][b][e] = 0.f;

    stage_load(gA, gB, s0,           0, tid);
    stage_load(gA, gB, s0 + STAGE_B, 1, tid);
    #pragma unroll 1
    for (int c = 0; c < NCHUNK; c++) {
        if (c < NCHUNK - 1) CP_WAIT1(); else CP_WAIT0();
        __syncthreads();
        if (c < NCHUNK - 2)
            stage_load(gA, gB, s0 + ((c + 2) % NSTAGE) * STAGE_B, c + 2, tid);
        compute_stage(s0 + (c % NSTAGE) * STAGE_B, wid, lane, acc);
    }
}

// ---------------- GEMM1: epilogue emits fp16 TMP ----------------
__global__ void __launch_bounds__(128, 3) k_gemm1() {
    extern __shared__ __align__(16) char dyn[];
    const int tid = threadIdx.x, wid = tid >> 5, lane = tid & 31;
    uint32_t s0 = (smem_u32(dyn) + 1023u) & ~1023u;

    const int bm = blockIdx.x * MT;    // m = b*256+i   (x = m for W L2 reuse)
    const int bn = blockIdx.y * NTL;   // n = k*512+q
    float acc[2][8][4];
    gemm_core(g_x1h + (size_t)bm * 512, g_wth + (size_t)bn * 512,
              s0, tid, wid, lane, acc);

    const int wm = (wid & 1) * 32, wn = (wid >> 1) * 64;
    const int quad = lane >> 2, tq = lane & 3;
    #pragma unroll
    for (int mg = 0; mg < 2; mg++) {
        #pragma unroll
        for (int pr = 0; pr < 2; pr++) {
            int m = bm + wm + mg * 16 + quad + pr * 8;
            size_t rowb = (size_t)m * 32768 + bn + wn + tq * 2;
            #pragma unroll
            for (int g = 0; g < 8; g++) {
                __half2 hv = __floats2half2_rn(acc[mg][g][pr * 2],
                                               acc[mg][g][pr * 2 + 1]);
                *(__half2*)(g_th + rowb + g * 8) = hv;
            }
        }
    }
}

// ---------------- GEMM2: out = X2_b . TMP_b^T + bias ----------------
__global__ void __launch_bounds__(128, 3) k_gemm2(const float* __restrict__ bias,
                                                  float* __restrict__ out) {
    extern __shared__ __align__(16) char dyn[];
    const int tid = threadIdx.x, wid = tid >> 5, lane = tid & 31;
    uint32_t s0 = (smem_u32(dyn) + 1023u) & ~1023u;

    const int bj = blockIdx.x * MT;    // j  (x = j for TMP L2 reuse)
    const int bn = blockIdx.y * NTL;   // r = i*64 + k
    const int b  = blockIdx.z;
    float acc[2][8][4];
    gemm_core(g_x2h + (size_t)b * 131072 + (size_t)bj * 512,
              g_th  + (size_t)b * 8388608 + (size_t)bn * 512,
              s0, tid, wid, lane, acc);

    const int wm = (wid & 1) * 32, wn = (wid >> 1) * 64;
    const int quad = lane >> 2, tq = lane & 3;
    const int ig = (bn + wn) >> 6;                  // wn in {0,64}: exact
    const size_t obase = ((size_t)b << 22) + (size_t)ig * 16384;
    #pragma unroll
    for (int g = 0; g < 8; g++) {
        int k = g * 8 + tq * 2;
        float2 bv = *(const float2*)(bias + k);
        #pragma unroll
        for (int mg = 0; mg < 2; mg++) {
            #pragma unroll
            for (int pr = 0; pr < 2; pr++) {
                int j = bj + wm + mg * 16 + quad + pr * 8;
                float2 v;
                v.x = acc[mg][g][pr * 2]     + bv.x;
                v.y = acc[mg][g][pr * 2 + 1] + bv.y;
                *(float2*)(out + obase + (size_t)j * 64 + k) = v;
            }
        }
    }
}

// ---------------- prep: fp32 -> fp16 ----------------
__global__ void __launch_bounds__(256) k_split(const float* __restrict__ in, int which) {
    __half* oh = which ? g_x2h : g_x1h;
    int i = blockIdx.x * 256 + threadIdx.x;      // 262144 float4s
    float4 v = ((const float4*)in)[i];
    ((__half2*)oh)[2 * i]     = __floats2half2_rn(v.x, v.y);
    ((__half2*)oh)[2 * i + 1] = __floats2half2_rn(v.z, v.w);
}

// W[k][p][q] -> Wt[k][q][p] fp16 (32x32 smem transpose tiles)
__global__ void __launch_bounds__(256) k_wtrans(const float* __restrict__ W) {
    __shared__ float t[32][33];
    int k = blockIdx.z;
    int q0 = blockIdx.x * 32, p0 = blockIdx.y * 32;
    int tx = threadIdx.x & 31, ty = threadIdx.x >> 5;
    const float* Wk = W + (size_t)k * 262144;
    #pragma unroll
    for (int s = 0; s < 4; s++)
        t[ty + s * 8][tx] = Wk[(size_t)(p0 + ty + s * 8) * 512 + q0 + tx];
    __syncthreads();
    #pragma unroll
    for (int s = 0; s < 4; s++) {
        int q = q0 + ty + s * 8;
        g_wth[(size_t)k * 262144 + (size_t)q * 512 + p0 + tx] =
            __float2half_rn(t[tx][ty + s * 8]);
    }
}

// ---------------- launch ----------------
extern "C" void kernel_launch(void* const* d_in, const int* in_sizes, int n_in,
                              void* d_out, int out_size) {
    const float* x1   = (const float*)d_in[0];
    const float* x2   = (const float*)d_in[1];
    const float* w    = (const float*)d_in[2];
    const float* bias = (const float*)d_in[3];
    float* out = (float*)d_out;

    cudaFuncSetAttribute(k_gemm1, cudaFuncAttributeMaxDynamicSharedMemorySize, SMEM_BYTES);
    cudaFuncSetAttribute(k_gemm2, cudaFuncAttributeMaxDynamicSharedMemorySize, SMEM_BYTES);

    k_split<<<1024, 256>>>(x1, 0);
    k_split<<<1024, 256>>>(x2, 1);
    k_wtrans<<<dim3(16, 16, 64), 256>>>(w);
    // GEMM1: x = m (32) so a wave shares W n-tiles across all m-blocks (L2 reuse)
    k_gemm1<<<dim3(32, 256), 128, SMEM_BYTES>>>();
    // GEMM2: x = j (4) so j-blocks of a TMP n-tile are co-resident
    k_gemm2<<<dim3(4, 128, 8), 128, SMEM_BYTES>>>(bias, out);
}

// round 14
// speedup vs baseline: 1.0385x; 1.0196x over previous
#include <cuda_runtime.h>
#include <cuda_fp16.h>
#include <cstdint>

// Bilinear out[b,i,j,k] = sum_{p,q} x1[b,i,p] W[k,p,q] x2[b,j,q] + bias[k]
// B=8, L=256, D1=D2=512, K=64.
// GEMM1: TMP[m=(b,i)][n=(k,q)] = X1[2048,512] . Wt[(k,q)][p]   (NT, inner 512)
// GEMM2: per b: C[j][r=(i,k)]  = X2_b[j][q] . TMP_b[r][q]      (NT, inner 512)
// Single-pass fp16 HMMA, CTA 64x128 (128 thr, 3 CTAs/SM).
// Round 14: register-pipelined fragment ping-pong — next k-step's LDSM issued
// under current k-step's MMAs, removing the LDSM->HMMA RAW from the loop.

#define DI __device__ __forceinline__

#define MT 64           // CTA m tile
#define NTL 128         // CTA n tile
#define KC 64           // k elements per chunk (128B rows fp16)
#define NCHUNK 8        // 512/64

#define TILE_A_B 8192           // 64 rows x 128B
#define TILE_B_B 16384          // 128 rows x 128B
#define STAGE_B (TILE_A_B + TILE_B_B)   // 24KB
#define NSTAGE 3
#define SMEM_BYTES (NSTAGE*STAGE_B + 1024)

// ---------------- scratch (device globals; allocs forbidden) ----------------
__device__ __half g_x1h[2048*512];
__device__ __half g_x2h[2048*512];
__device__ __half g_wth[64*512*512];    // Wt[k][q][p]
__device__ __half g_th[2048u*32768u];   // TMP [m][n]

// ---------------- PTX helpers ----------------
DI uint32_t smem_u32(const void* p) {
    uint32_t a;
    asm("{ .reg .u64 t; cvta.to.shared.u64 t, %1; cvt.u32.u64 %0, t; }"
        : "=r"(a) : "l"(p));
    return a;
}
DI void cp16(uint32_t dst, const void* src) {
    asm volatile("cp.async.cg.shared.global [%0], [%1], 16;"
                 :: "r"(dst), "l"(src) : "memory");
}
#define CP_COMMIT() asm volatile("cp.async.commit_group;" ::: "memory")
#define CP_WAIT1()  asm volatile("cp.async.wait_group 1;"  ::: "memory")
#define CP_WAIT0()  asm volatile("cp.async.wait_group 0;"  ::: "memory")

DI void ldsm4(uint32_t addr, uint32_t r[4]) {
    asm volatile("ldmatrix.sync.aligned.m8n8.x4.shared.b16 {%0,%1,%2,%3}, [%4];"
        : "=r"(r[0]), "=r"(r[1]), "=r"(r[2]), "=r"(r[3]) : "r"(addr));
}
DI void mma16816(float c[4], const uint32_t a[4], uint32_t b0, uint32_t b1) {
    asm volatile("mma.sync.aligned.m16n8k16.row.col.f32.f16.f16.f32 "
        "{%0,%1,%2,%3}, {%4,%5,%6,%7}, {%8,%9}, {%0,%1,%2,%3};"
        : "+f"(c[0]), "+f"(c[1]), "+f"(c[2]), "+f"(c[3])
        : "r"(a[0]), "r"(a[1]), "r"(a[2]), "r"(a[3]), "r"(b0), "r"(b1));
}

// ---------------- stage loader: A(64r) + B(128r) K-major tiles, 128 threads ----
DI void stage_load(const __half* __restrict__ gA, const __half* __restrict__ gB,
                   uint32_t sbase, int chunk, int tid) {
    #pragma unroll
    for (int i = 0; i < 4; i++) {                 // A: 512 granules
        int g   = tid + i * 128;
        int row = g >> 3;
        int c   = g & 7;
        uint32_t dst = sbase + (uint32_t)(row * 128 + ((c ^ (row & 7)) << 4));
        cp16(dst, gA + (size_t)row * 512 + chunk * KC + c * 8);
    }
    #pragma unroll
    for (int i = 0; i < 8; i++) {                 // B: 1024 granules
        int g   = tid + i * 128;
        int row = g >> 3;
        int c   = g & 7;
        uint32_t dst = sbase + TILE_A_B + (uint32_t)(row * 128 + ((c ^ (row & 7)) << 4));
        cp16(dst, gB + (size_t)row * 512 + chunk * KC + c * 8);
    }
    CP_COMMIT();
}

// ---------------- fragment loaders ----------------
DI void ldsA(uint32_t sA, int wm, int lr, int ls, int kg, uint32_t ah[2][4]) {
    #pragma unroll
    for (int mg = 0; mg < 2; mg++) {
        int row = wm + mg * 16 + lr;
        uint32_t off = (uint32_t)(row * 128 + (((kg + ls) ^ (row & 7)) << 4));
        ldsm4(sA + off, ah[mg]);
    }
}
DI void ldsB(uint32_t sB, int wn, int lr, int ls, int kg, uint32_t bh[4][4]) {
    #pragma unroll
    for (int h = 0; h < 4; h++) {
        int row = wn + h * 16 + lr;
        uint32_t off = (uint32_t)(row * 128 + (((kg + ls) ^ (row & 7)) << 4));
        ldsm4(sB + off, bh[h]);
    }
}

// ---------------- compute one 64-wide K chunk (reg ping-pong) ----------------
DI void compute_stage(uint32_t s, int wid, int lane, float acc[2][8][4]) {
    const int wm = (wid & 1) * 32;
    const int wn = (wid >> 1) * 64;
    const int lr = lane & 15;
    const int ls = lane >> 4;
    const uint32_t sA = s;
    const uint32_t sB = s + TILE_A_B;

    uint32_t ah[2][2][4], bh[2][4][4];
    ldsA(sA, wm, lr, ls, 0, ah[0]);
    ldsB(sB, wn, lr, ls, 0, bh[0]);
    #pragma unroll
    for (int ks = 0; ks < 4; ks++) {
        const int cur = ks & 1, nxt = cur ^ 1;
        if (ks < 3) {                         // prefetch next k-step under MMAs
            ldsA(sA, wm, lr, ls, (ks + 1) * 2, ah[nxt]);
            ldsB(sB, wn, lr, ls, (ks + 1) * 2, bh[nxt]);
        }
        #pragma unroll
        for (int h = 0; h < 4; h++)
            #pragma unroll
            for (int mg = 0; mg < 2; mg++) {
                mma16816(acc[mg][2*h],   ah[cur][mg], bh[cur][h][0], bh[cur][h][2]);
                mma16816(acc[mg][2*h+1], ah[cur][mg], bh[cur][h][1], bh[cur][h][3]);
            }
    }
}

// ---------------- shared mainloop (3-stage pipeline, 1 sync/chunk) ----------
DI void gemm_core(const __half* gA, const __half* gB,
                  uint32_t s0, int tid, int wid, int lane, float acc[2][8][4]) {
    #pragma unroll
    for (int a = 0; a < 2; a++)
        #pragma unroll
        for (int b = 0; b < 8; b++)
            #pragma unroll
            for (int e = 0; e < 4; e++) acc[a][b][e] = 0.f;

    stage_load(gA, gB, s0,           0, tid);
    stage_load(gA, gB, s0 + STAGE_B, 1, tid);
    #pragma unroll 1
    for (int c = 0; c < NCHUNK; c++) {
        if (c < NCHUNK - 1) CP_WAIT1(); else CP_WAIT0();
        __syncthreads();
        if (c < NCHUNK - 2)
            stage_load(gA, gB, s0 + ((c + 2) % NSTAGE) * STAGE_B, c + 2, tid);
        compute_stage(s0 + (c % NSTAGE) * STAGE_B, wid, lane, acc);
    }
}

// ---------------- GEMM1: epilogue emits fp16 TMP ----------------
__global__ void __launch_bounds__(128, 3) k_gemm1() {
    extern __shared__ __align__(16) char dyn[];
    const int tid = threadIdx.x, wid = tid >> 5, lane = tid & 31;
    uint32_t s0 = (smem_u32(dyn) + 1023u) & ~1023u;

    const int bm = blockIdx.x * MT;    // m = b*256+i   (x = m for W L2 reuse)
    const int bn = blockIdx.y * NTL;   // n = k*512+q
    float acc[2][8][4];
    gemm_core(g_x1h + (size_t)bm * 512, g_wth + (size_t)bn * 512,
              s0, tid, wid, lane, acc);

    const int wm = (wid & 1) * 32, wn = (wid >> 1) * 64;
    const int quad = lane >> 2, tq = lane & 3;
    #pragma unroll
    for (int mg = 0; mg < 2; mg++) {
        #pragma unroll
        for (int pr = 0; pr < 2; pr++) {
            int m = bm + wm + mg * 16 + quad + pr * 8;
            size_t rowb = (size_t)m * 32768 + bn + wn + tq * 2;
            #pragma unroll
            for (int g = 0; g < 8; g++) {
                __half2 hv = __floats2half2_rn(acc[mg][g][pr * 2],
                                               acc[mg][g][pr * 2 + 1]);
                *(__half2*)(g_th + rowb + g * 8) = hv;
            }
        }
    }
}

// ---------------- GEMM2: out = X2_b . TMP_b^T + bias ----------------
__global__ void __launch_bounds__(128, 3) k_gemm2(const float* __restrict__ bias,
                                                  float* __restrict__ out) {
    extern __shared__ __align__(16) char dyn[];
    const int tid = threadIdx.x, wid = tid >> 5, lane = tid & 31;
    uint32_t s0 = (smem_u32(dyn) + 1023u) & ~1023u;

    const int bj = blockIdx.x * MT;    // j  (x = j for TMP L2 reuse)
    const int bn = blockIdx.y * NTL;   // r = i*64 + k
    const int b  = blockIdx.z;
    float acc[2][8][4];
    gemm_core(g_x2h + (size_t)b * 131072 + (size_t)bj * 512,
              g_th  + (size_t)b * 8388608 + (size_t)bn * 512,
              s0, tid, wid, lane, acc);

    const int wm = (wid & 1) * 32, wn = (wid >> 1) * 64;
    const int quad = lane >> 2, tq = lane & 3;
    const int ig = (bn + wn) >> 6;                  // wn in {0,64}: exact
    const size_t obase = ((size_t)b << 22) + (size_t)ig * 16384;
    #pragma unroll
    for (int g = 0; g < 8; g++) {
        int k = g * 8 + tq * 2;
        float2 bv = *(const float2*)(bias + k);
        #pragma unroll
        for (int mg = 0; mg < 2; mg++) {
            #pragma unroll
            for (int pr = 0; pr < 2; pr++) {
                int j = bj + wm + mg * 16 + quad + pr * 8;
                float2 v;
                v.x = acc[mg][g][pr * 2]     + bv.x;
                v.y = acc[mg][g][pr * 2 + 1] + bv.y;
                *(float2*)(out + obase + (size_t)j * 64 + k) = v;
            }
        }
    }
}

// ---------------- prep: fp32 -> fp16 (both inputs, one launch) ----------------
__global__ void __launch_bounds__(256) k_split2(const float* __restrict__ x1,
                                                const float* __restrict__ x2) {
    int i = blockIdx.x * 256 + threadIdx.x;      // 524288 float4s total
    const float* in;
    __half* oh;
    int idx;
    if (i < 262144) { in = x1; oh = g_x1h; idx = i; }
    else            { in = x2; oh = g_x2h; idx = i - 262144; }
    float4 v = ((const float4*)in)[idx];
    ((__half2*)oh)[2 * idx]     = __floats2half2_rn(v.x, v.y);
    ((__half2*)oh)[2 * idx + 1] = __floats2half2_rn(v.z, v.w);
}

// W[k][p][q] -> Wt[k][q][p] fp16 (32x32 smem transpose tiles)
__global__ void __launch_bounds__(256) k_wtrans(const float* __restrict__ W) {
    __shared__ float t[32][33];
    int k = blockIdx.z;
    int q0 = blockIdx.x * 32, p0 = blockIdx.y * 32;
    int tx = threadIdx.x & 31, ty = threadIdx.x >> 5;
    const float* Wk = W + (size_t)k * 262144;
    #pragma unroll
    for (int s = 0; s < 4; s++)
        t[ty + s * 8][tx] = Wk[(size_t)(p0 + ty + s * 8) * 512 + q0 + tx];
    __syncthreads();
    #pragma unroll
    for (int s = 0; s < 4; s++) {
        int q = q0 + ty + s * 8;
        g_wth[(size_t)k * 262144 + (size_t)q * 512 + p0 + tx] =
            __float2half_rn(t[tx][ty + s * 8]);
    }
}

// ---------------- launch ----------------
extern "C" void kernel_launch(void* const* d_in, const int* in_sizes, int n_in,
                              void* d_out, int out_size) {
    const float* x1   = (const float*)d_in[0];
    const float* x2   = (const float*)d_in[1];
    const float* w    = (const float*)d_in[2];
    const float* bias = (const float*)d_in[3];
    float* out = (float*)d_out;

    cudaFuncSetAttribute(k_gemm1, cudaFuncAttributeMaxDynamicSharedMemorySize, SMEM_BYTES);
    cudaFuncSetAttribute(k_gemm2, cudaFuncAttributeMaxDynamicSharedMemorySize, SMEM_BYTES);

    k_split2<<<2048, 256>>>(x1, x2);
    k_wtrans<<<dim3(16, 16, 64), 256>>>(w);
    // GEMM1: x = m (32) so a wave shares W n-tiles across all m-blocks (L2 reuse)
    k_gemm1<<<dim3(32, 256), 128, SMEM_BYTES>>>();
    // GEMM2: x = j (4) so j-blocks of a TMP n-tile are co-resident
    k_gemm2<<<dim3(4, 128, 8), 128, SMEM_BYTES>>>(bias, out);
}

// round 15
// speedup vs baseline: 1.0395x; 1.0010x over previous
#include <cuda_runtime.h>
#include <cuda_fp16.h>
#include <cstdint>

// Bilinear out[b,i,j,k] = sum_{p,q} x1[b,i,p] W[k,p,q] x2[b,j,q] + bias[k]
// B=8, L=256, D1=D2=512, K=64.
// GEMM1: TMP[m=(b,i)][n=(k,q)] = X1[2048,512] . Wt[(k,q)][p]   (NT, inner 512)
// GEMM2: per b: C[j][r=(i,k)]  = X2_b[j][q] . TMP_b[r][q]      (NT, inner 512)
// Single-pass fp16 HMMA, CTA 64x128 (128 thr, 3 CTAs/SM), reg ping-pong.
// Measured: both GEMMs sit at the legacy-HMMA issue wall (~57% tensor duty,
// ~610 MAC/cyc/SM) — round 15 compresses the remaining prep/launch overhead:
// W-transpose + X1/X2 fp16 conversion fused into ONE heterogeneous-grid kernel.

#define DI __device__ __forceinline__

#define MT 64           // CTA m tile
#define NTL 128         // CTA n tile
#define KC 64           // k elements per chunk (128B rows fp16)
#define NCHUNK 8        // 512/64

#define TILE_A_B 8192           // 64 rows x 128B
#define TILE_B_B 16384          // 128 rows x 128B
#define STAGE_B (TILE_A_B + TILE_B_B)   // 24KB
#define NSTAGE 3
#define SMEM_BYTES (NSTAGE*STAGE_B + 1024)

// ---------------- scratch (device globals; allocs forbidden) ----------------
__device__ __half g_x1h[2048*512];
__device__ __half g_x2h[2048*512];
__device__ __half g_wth[64*512*512];    // Wt[k][q][p]
__device__ __half g_th[2048u*32768u];   // TMP [m][n]

// ---------------- PTX helpers ----------------
DI uint32_t smem_u32(const void* p) {
    uint32_t a;
    asm("{ .reg .u64 t; cvta.to.shared.u64 t, %1; cvt.u32.u64 %0, t; }"
        : "=r"(a) : "l"(p));
    return a;
}
DI void cp16(uint32_t dst, const void* src) {
    asm volatile("cp.async.cg.shared.global [%0], [%1], 16;"
                 :: "r"(dst), "l"(src) : "memory");
}
#define CP_COMMIT() asm volatile("cp.async.commit_group;" ::: "memory")
#define CP_WAIT1()  asm volatile("cp.async.wait_group 1;"  ::: "memory")
#define CP_WAIT0()  asm volatile("cp.async.wait_group 0;"  ::: "memory")

DI void ldsm4(uint32_t addr, uint32_t r[4]) {
    asm volatile("ldmatrix.sync.aligned.m8n8.x4.shared.b16 {%0,%1,%2,%3}, [%4];"
        : "=r"(r[0]), "=r"(r[1]), "=r"(r[2]), "=r"(r[3]) : "r"(addr));
}
DI void mma16816(float c[4], const uint32_t a[4], uint32_t b0, uint32_t b1) {
    asm volatile("mma.sync.aligned.m16n8k16.row.col.f32.f16.f16.f32 "
        "{%0,%1,%2,%3}, {%4,%5,%6,%7}, {%8,%9}, {%0,%1,%2,%3};"
        : "+f"(c[0]), "+f"(c[1]), "+f"(c[2]), "+f"(c[3])
        : "r"(a[0]), "r"(a[1]), "r"(a[2]), "r"(a[3]), "r"(b0), "r"(b1));
}

// ---------------- stage loader: A(64r) + B(128r) K-major tiles, 128 threads ----
DI void stage_load(const __half* __restrict__ gA, const __half* __restrict__ gB,
                   uint32_t sbase, int chunk, int tid) {
    #pragma unroll
    for (int i = 0; i < 4; i++) {                 // A: 512 granules
        int g   = tid + i * 128;
        int row = g >> 3;
        int c   = g & 7;
        uint32_t dst = sbase + (uint32_t)(row * 128 + ((c ^ (row & 7)) << 4));
        cp16(dst, gA + (size_t)row * 512 + chunk * KC + c * 8);
    }
    #pragma unroll
    for (int i = 0; i < 8; i++) {                 // B: 1024 granules
        int g   = tid + i * 128;
        int row = g >> 3;
        int c   = g & 7;
        uint32_t dst = sbase + TILE_A_B + (uint32_t)(row * 128 + ((c ^ (row & 7)) << 4));
        cp16(dst, gB + (size_t)row * 512 + chunk * KC + c * 8);
    }
    CP_COMMIT();
}

// ---------------- fragment loaders ----------------
DI void ldsA(uint32_t sA, int wm, int lr, int ls, int kg, uint32_t ah[2][4]) {
    #pragma unroll
    for (int mg = 0; mg < 2; mg++) {
        int row = wm + mg * 16 + lr;
        uint32_t off = (uint32_t)(row * 128 + (((kg + ls) ^ (row & 7)) << 4));
        ldsm4(sA + off, ah[mg]);
    }
}
DI void ldsB(uint32_t sB, int wn, int lr, int ls, int kg, uint32_t bh[4][4]) {
    #pragma unroll
    for (int h = 0; h < 4; h++) {
        int row = wn + h * 16 + lr;
        uint32_t off = (uint32_t)(row * 128 + (((kg + ls) ^ (row & 7)) << 4));
        ldsm4(sB + off, bh[h]);
    }
}

// ---------------- compute one 64-wide K chunk (reg ping-pong) ----------------
DI void compute_stage(uint32_t s, int wid, int lane, float acc[2][8][4]) {
    const int wm = (wid & 1) * 32;
    const int wn = (wid >> 1) * 64;
    const int lr = lane & 15;
    const int ls = lane >> 4;
    const uint32_t sA = s;
    const uint32_t sB = s + TILE_A_B;

    uint32_t ah[2][2][4], bh[2][4][4];
    ldsA(sA, wm, lr, ls, 0, ah[0]);
    ldsB(sB, wn, lr, ls, 0, bh[0]);
    #pragma unroll
    for (int ks = 0; ks < 4; ks++) {
        const int cur = ks & 1, nxt = cur ^ 1;
        if (ks < 3) {                         // prefetch next k-step under MMAs
            ldsA(sA, wm, lr, ls, (ks + 1) * 2, ah[nxt]);
            ldsB(sB, wn, lr, ls, (ks + 1) * 2, bh[nxt]);
        }
        #pragma unroll
        for (int h = 0; h < 4; h++)
            #pragma unroll
            for (int mg = 0; mg < 2; mg++) {
                mma16816(acc[mg][2*h],   ah[cur][mg], bh[cur][h][0], bh[cur][h][2]);
                mma16816(acc[mg][2*h+1], ah[cur][mg], bh[cur][h][1], bh[cur][h][3]);
            }
    }
}

// ---------------- shared mainloop (3-stage pipeline, 1 sync/chunk) ----------
DI void gemm_core(const __half* gA, const __half* gB,
                  uint32_t s0, int tid, int wid, int lane, float acc[2][8][4]) {
    #pragma unroll
    for (int a = 0; a < 2; a++)
        #pragma unroll
        for (int b = 0; b < 8; b++)
            #pragma unroll
            for (int e = 0; e < 4; e++) acc[a][b][e] = 0.f;

    stage_load(gA, gB, s0,           0, tid);
    stage_load(gA, gB, s0 + STAGE_B, 1, tid);
    #pragma unroll 1
    for (int c = 0; c < NCHUNK; c++) {
        if (c < NCHUNK - 1) CP_WAIT1(); else CP_WAIT0();
        __syncthreads();
        if (c < NCHUNK - 2)
            stage_load(gA, gB, s0 + ((c + 2) % NSTAGE) * STAGE_B, c + 2, tid);
        compute_stage(s0 + (c % NSTAGE) * STAGE_B, wid, lane, acc);
    }
}

// ---------------- GEMM1: epilogue emits fp16 TMP ----------------
__global__ void __launch_bounds__(128, 3) k_gemm1() {
    extern __shared__ __align__(16) char dyn[];
    const int tid = threadIdx.x, wid = tid >> 5, lane = tid & 31;
    uint32_t s0 = (smem_u32(dyn) + 1023u) & ~1023u;

    const int bm = blockIdx.x * MT;    // m = b*256+i   (x = m for W L2 reuse)
    const int bn = blockIdx.y * NTL;   // n = k*512+q
    float acc[2][8][4];
    gemm_core(g_x1h + (size_t)bm * 512, g_wth + (size_t)bn * 512,
              s0, tid, wid, lane, acc);

    const int wm = (wid & 1) * 32, wn = (wid >> 1) * 64;
    const int quad = lane >> 2, tq = lane & 3;
    #pragma unroll
    for (int mg = 0; mg < 2; mg++) {
        #pragma unroll
        for (int pr = 0; pr < 2; pr++) {
            int m = bm + wm + mg * 16 + quad + pr * 8;
            size_t rowb = (size_t)m * 32768 + bn + wn + tq * 2;
            #pragma unroll
            for (int g = 0; g < 8; g++) {
                __half2 hv = __floats2half2_rn(acc[mg][g][pr * 2],
                                               acc[mg][g][pr * 2 + 1]);
                *(__half2*)(g_th + rowb + g * 8) = hv;
            }
        }
    }
}

// ---------------- GEMM2: out = X2_b . TMP_b^T + bias ----------------
__global__ void __launch_bounds__(128, 3) k_gemm2(const float* __restrict__ bias,
                                                  float* __restrict__ out) {
    extern __shared__ __align__(16) char dyn[];
    const int tid = threadIdx.x, wid = tid >> 5, lane = tid & 31;
    uint32_t s0 = (smem_u32(dyn) + 1023u) & ~1023u;

    const int bj = blockIdx.x * MT;    // j  (x = j for TMP L2 reuse)
    const int bn = blockIdx.y * NTL;   // r = i*64 + k
    const int b  = blockIdx.z;
    float acc[2][8][4];
    gemm_core(g_x2h + (size_t)b * 131072 + (size_t)bj * 512,
              g_th  + (size_t)b * 8388608 + (size_t)bn * 512,
              s0, tid, wid, lane, acc);

    const int wm = (wid & 1) * 32, wn = (wid >> 1) * 64;
    const int quad = lane >> 2, tq = lane & 3;
    const int ig = (bn + wn) >> 6;                  // wn in {0,64}: exact
    const size_t obase = ((size_t)b << 22) + (size_t)ig * 16384;
    #pragma unroll
    for (int g = 0; g < 8; g++) {
        int k = g * 8 + tq * 2;
        float2 bv = *(const float2*)(bias + k);
        #pragma unroll
        for (int mg = 0; mg < 2; mg++) {
            #pragma unroll
            for (int pr = 0; pr < 2; pr++) {
                int j = bj + wm + mg * 16 + quad + pr * 8;
                float2 v;
                v.x = acc[mg][g][pr * 2]     + bv.x;
                v.y = acc[mg][g][pr * 2 + 1] + bv.y;
                *(float2*)(out + obase + (size_t)j * 64 + k) = v;
            }
        }
    }
}

// ---------------- fused prep: W transpose + X1/X2 fp16, ONE launch ----------
// blocks [0, 16384):  W[k][p][q] -> Wt[k][q][p] fp16 (32x32 smem transpose)
// blocks [16384, 18432): X1/X2 fp32 -> fp16 streaming convert
__global__ void __launch_bounds__(256) k_prep(const float* __restrict__ x1,
                                              const float* __restrict__ x2,
                                              const float* __restrict__ W) {
    __shared__ float t[32][33];
    const int bx = blockIdx.x;
    if (bx < 16384) {
        const int k  = bx >> 8;
        const int q0 = (bx & 15) << 5;
        const int p0 = ((bx >> 4) & 15) << 5;
        const int tx = threadIdx.x & 31, ty = threadIdx.x >> 5;
        const float* Wk = W + (size_t)k * 262144;
        #pragma unroll
        for (int s = 0; s < 4; s++)
            t[ty + s * 8][tx] = Wk[(size_t)(p0 + ty + s * 8) * 512 + q0 + tx];
        __syncthreads();
        #pragma unroll
        for (int s = 0; s < 4; s++) {
            int q = q0 + ty + s * 8;
            g_wth[(size_t)k * 262144 + (size_t)q * 512 + p0 + tx] =
                __float2half_rn(t[tx][ty + s * 8]);
        }
    } else {
        int i = (bx - 16384) * 256 + threadIdx.x;    // 524288 float4s total
        const float* in;
        __half* oh;
        int idx;
        if (i < 262144) { in = x1; oh = g_x1h; idx = i; }
        else            { in = x2; oh = g_x2h; idx = i - 262144; }
        float4 v = ((const float4*)in)[idx];
        ((__half2*)oh)[2 * idx]     = __floats2half2_rn(v.x, v.y);
        ((__half2*)oh)[2 * idx + 1] = __floats2half2_rn(v.z, v.w);
    }
}

// ---------------- launch ----------------
extern "C" void kernel_launch(void* const* d_in, const int* in_sizes, int n_in,
                              void* d_out, int out_size) {
    const float* x1   = (const float*)d_in[0];
    const float* x2   = (const float*)d_in[1];
    const float* w    = (const float*)d_in[2];
    const float* bias = (const float*)d_in[3];
    float* out = (float*)d_out;

    cudaFuncSetAttribute(k_gemm1, cudaFuncAttributeMaxDynamicSharedMemorySize, SMEM_BYTES);
    cudaFuncSetAttribute(k_gemm2, cudaFuncAttributeMaxDynamicSharedMemorySize, SMEM_BYTES);

    k_prep<<<18432, 256>>>(x1, x2, w);
    // GEMM1: x = m (32) so a wave shares W n-tiles across all m-blocks (L2 reuse)
    k_gemm1<<<dim3(32, 256), 128, SMEM_BYTES>>>();
    // GEMM2: x = j (4) so j-blocks of a TMP n-tile are co-resident
    k_gemm2<<<dim3(4, 128, 8), 128, SMEM_BYTES>>>(bias, out);
}